// round 8
// baseline (speedup 1.0000x reference)
#include <cuda_runtime.h>
#include <cuda_bf16.h>
#include <math.h>
#include <stdint.h>

#define NB      8
#define SEQ     1024
#define DIM     512
#define NHEADS  8
#define DHEAD   64
#define INNER   512
#define M_TOT   (NB*SEQ)        /* 8192 */
#define BH      (NB*NHEADS)     /* 64 */

// ---- scratch (allocation-free: __device__ globals) ----
__device__ __nv_bfloat16 g_xhi [(size_t)M_TOT*DIM];     // pre-split x
__device__ __nv_bfloat16 g_xlo [(size_t)M_TOT*DIM];
__device__ __nv_bfloat16 g_aohi[(size_t)M_TOT*INNER];   // attn out, split
__device__ __nv_bfloat16 g_aolo[(size_t)M_TOT*INNER];
// pre-split bf16 q/k/v, [bh][n][d]; q has exp(temperature)*log2(e) folded in
__device__ __nv_bfloat16 g_qhi[(size_t)BH*SEQ*DHEAD];
__device__ __nv_bfloat16 g_qlo[(size_t)BH*SEQ*DHEAD];
__device__ __nv_bfloat16 g_khi[(size_t)BH*SEQ*DHEAD];
__device__ __nv_bfloat16 g_klo[(size_t)BH*SEQ*DHEAD];
__device__ __nv_bfloat16 g_vhi[(size_t)BH*SEQ*DHEAD];
__device__ __nv_bfloat16 g_vlo[(size_t)BH*SEQ*DHEAD];
// pre-transposed + split weights: [n][k] bf16
__device__ __nv_bfloat16 g_wqkv_hi[(size_t)3*INNER*DIM];
__device__ __nv_bfloat16 g_wqkv_lo[(size_t)3*INNER*DIM];
__device__ __nv_bfloat16 g_wout_hi[(size_t)DIM*INNER];
__device__ __nv_bfloat16 g_wout_lo[(size_t)DIM*INNER];

// ========================== helpers ===========================
__device__ __forceinline__ uint32_t smem_u32(const void* p) {
    uint32_t a;
    asm("{ .reg .u64 t; cvta.to.shared.u64 t, %1; cvt.u32.u64 %0, t; }" : "=r"(a) : "l"(p));
    return a;
}
__device__ __forceinline__ void ldm_x4(uint32_t* f, uint32_t addr) {
    asm volatile("ldmatrix.sync.aligned.m8n8.x4.shared.b16 {%0,%1,%2,%3}, [%4];"
                 : "=r"(f[0]), "=r"(f[1]), "=r"(f[2]), "=r"(f[3]) : "r"(addr));
}
__device__ __forceinline__ void ldm_x4t(uint32_t* f, uint32_t addr) {
    asm volatile("ldmatrix.sync.aligned.m8n8.x4.trans.shared.b16 {%0,%1,%2,%3}, [%4];"
                 : "=r"(f[0]), "=r"(f[1]), "=r"(f[2]), "=r"(f[3]) : "r"(addr));
}
// non-volatile: pure register computation, let the compiler schedule freely
__device__ __forceinline__ void mma_bf16(float* d, const uint32_t* a, const uint32_t* b) {
    asm("mma.sync.aligned.m16n8k16.row.col.f32.bf16.bf16.f32 "
        "{%0,%1,%2,%3}, {%4,%5,%6,%7}, {%8,%9}, {%0,%1,%2,%3};"
        : "+f"(d[0]), "+f"(d[1]), "+f"(d[2]), "+f"(d[3])
        : "r"(a[0]), "r"(a[1]), "r"(a[2]), "r"(a[3]), "r"(b[0]), "r"(b[1]));
}
__device__ __forceinline__ uint32_t pack_hi(float x, float y) {
    __nv_bfloat162 h = {__float2bfloat16(x), __float2bfloat16(y)};
    return *(uint32_t*)&h;
}
__device__ __forceinline__ uint32_t pack_lo(float x, float y) {
    float rx = x - __bfloat162float(__float2bfloat16(x));
    float ry = y - __bfloat162float(__float2bfloat16(y));
    __nv_bfloat162 l = {__float2bfloat16(rx), __float2bfloat16(ry)};
    return *(uint32_t*)&l;
}
__device__ __forceinline__ void cp16(uint32_t sdst, const void* gsrc) {
    asm volatile("cp.async.cg.shared.global [%0], [%1], 16;" :: "r"(sdst), "l"(gsrc));
}
__device__ __forceinline__ void cp_commit() { asm volatile("cp.async.commit_group;"); }
template <int N> __device__ __forceinline__ void cp_wait() {
    asm volatile("cp.async.wait_group %0;" :: "n"(N));
}

// ============================================================================
// Prep: split x fp32 -> bf16 hi/lo (same layout)
// ============================================================================
__global__ __launch_bounds__(256) void xsplit_kernel(const float* __restrict__ X)
{
    size_t i = ((size_t)blockIdx.x * 256 + threadIdx.x) * 4;
    float4 v = *(const float4*)&X[i];
    *(uint2*)&g_xhi[i] = make_uint2(pack_hi(v.x, v.y), pack_hi(v.z, v.w));
    *(uint2*)&g_xlo[i] = make_uint2(pack_lo(v.x, v.y), pack_lo(v.z, v.w));
}

// ============================================================================
// Prep: transpose [512][N] fp32 -> [N][512] bf16 (hi, lo split)
// ============================================================================
__global__ void wsplit_kernel(const float* __restrict__ W,
                              __nv_bfloat16* __restrict__ hi,
                              __nv_bfloat16* __restrict__ lo, int N)
{
    __shared__ float t[32][33];
    int n = blockIdx.x * 32 + threadIdx.x;
    int k = blockIdx.y * 32 + threadIdx.y;
    t[threadIdx.y][threadIdx.x] = W[(size_t)k * N + n];
    __syncthreads();
    int n2 = blockIdx.x * 32 + threadIdx.y;
    int k2 = blockIdx.y * 32 + threadIdx.x;
    float v = t[threadIdx.x][threadIdx.y];
    __nv_bfloat16 h = __float2bfloat16(v);
    hi[(size_t)n2 * DIM + k2] = h;
    lo[(size_t)n2 * DIM + k2] = __float2bfloat16(v - __bfloat162float(h));
}

// ============================================================================
// HMMA GEMM, 2-stage cp.async pipeline. Tile 128x128, BK=32, 8 warps (4x2).
// Split-bf16 3-MMA emitted as hh/hl/lh sweeps (no same-acc dependent chains).
// mode 0: epilogue scatters q(scaled)/k/v to bf16 [bh][n][d]; mode 1: fp32 C.
// ============================================================================
#define BK   32
#define PAD  40
#define GST  10240                 /* bytes per 128xPAD bf16 buffer */
#define GSTAGE (4*GST)             /* Ahi,Alo,Bhi,Blo */

__global__ __launch_bounds__(256, 2) void gemm_hmma_kernel(
    const __nv_bfloat16* __restrict__ Ahi,
    const __nv_bfloat16* __restrict__ Alo,
    const __nv_bfloat16* __restrict__ Bhi,
    const __nv_bfloat16* __restrict__ Blo,
    float* __restrict__ C, const float* __restrict__ temp, int mode)
{
    extern __shared__ char smem[];
    const uint32_t uS = smem_u32(smem);

    const int tx   = threadIdx.x;
    const int lane = tx & 31;
    const int wid  = tx >> 5;
    const int wm   = wid >> 1;
    const int wn   = wid & 1;
    const int row0 = blockIdx.y * 128;
    const int col0 = blockIdx.x * 128;

    const int cr = tx >> 2;
    const int cc = (tx & 3) << 3;
    auto issue = [&](int kc, int s) {
        uint32_t sb = uS + s * GSTAGE;
#pragma unroll
        for (int t = 0; t < 2; t++) {
            int r = cr + t * 64;
            uint32_t so = (uint32_t)(r * PAD + cc) * 2;
            size_t  ga = (size_t)(row0 + r) * DIM + kc + cc;
            size_t  gb = (size_t)(col0 + r) * DIM + kc + cc;
            cp16(sb + so,           Ahi + ga);
            cp16(sb + GST   + so,   Alo + ga);
            cp16(sb + 2*GST + so,   Bhi + gb);
            cp16(sb + 3*GST + so,   Blo + gb);
        }
        cp_commit();
    };

    float acc[2][8][4];
#pragma unroll
    for (int i = 0; i < 2; i++)
#pragma unroll
        for (int j = 0; j < 8; j++)
#pragma unroll
            for (int t = 0; t < 4; t++) acc[i][j][t] = 0.f;

    const int a_row  = lane & 15;
    const int a_half = lane >> 4;
    const int b_row  = (lane & 7) + ((lane >> 4) << 3);
    const int b_half = (lane >> 3) & 1;

    issue(0, 0);
    const int KITER = DIM / BK;        // 16
    for (int kc = 0; kc < KITER; kc++) {
        if (kc + 1 < KITER) { issue((kc + 1) * BK, (kc + 1) & 1); cp_wait<1>(); }
        else                { cp_wait<0>(); }
        __syncthreads();

        const uint32_t sb = uS + (kc & 1) * GSTAGE;
        const uint32_t uAhi = sb, uAlo = sb + GST, uBhi = sb + 2*GST, uBlo = sb + 3*GST;
#pragma unroll
        for (int kk = 0; kk < 2; kk++) {
            uint32_t afh[2][4], afl[2][4];
#pragma unroll
            for (int mf = 0; mf < 2; mf++) {
                uint32_t boff = (uint32_t)((wm * 32 + mf * 16 + a_row) * PAD + kk * 16) * 2
                              + a_half * 16;
                ldm_x4(afh[mf], uAhi + boff);
                ldm_x4(afl[mf], uAlo + boff);
            }
            uint32_t bfh[8][2], bfl[8][2];
#pragma unroll
            for (int nf2 = 0; nf2 < 4; nf2++) {
                uint32_t boff = (uint32_t)((wn * 64 + nf2 * 16 + b_row) * PAD + kk * 16) * 2
                              + b_half * 16;
                uint32_t th[4], tl[4];
                ldm_x4(th, uBhi + boff);
                ldm_x4(tl, uBlo + boff);
                bfh[nf2*2][0] = th[0]; bfh[nf2*2][1] = th[1];
                bfh[nf2*2+1][0] = th[2]; bfh[nf2*2+1][1] = th[3];
                bfl[nf2*2][0] = tl[0]; bfl[nf2*2][1] = tl[1];
                bfl[nf2*2+1][0] = tl[2]; bfl[nf2*2+1][1] = tl[3];
            }
            // hh sweep, then hl, then lh: 16 independent accs between touches
#pragma unroll
            for (int mf = 0; mf < 2; mf++)
#pragma unroll
                for (int nf = 0; nf < 8; nf++)
                    mma_bf16(acc[mf][nf], afh[mf], bfh[nf]);
#pragma unroll
            for (int mf = 0; mf < 2; mf++)
#pragma unroll
                for (int nf = 0; nf < 8; nf++)
                    mma_bf16(acc[mf][nf], afh[mf], bfl[nf]);
#pragma unroll
            for (int mf = 0; mf < 2; mf++)
#pragma unroll
                for (int nf = 0; nf < 8; nf++)
                    mma_bf16(acc[mf][nf], afl[mf], bfh[nf]);
        }
        __syncthreads();
    }

    // q gets exp(temperature) * log2(e) so attention can use exp2
    const float sc = (mode == 0) ? __expf(*temp) * 1.44269504f : 1.f;
#pragma unroll
    for (int mf = 0; mf < 2; mf++) {
        int m_base = row0 + wm * 32 + mf * 16 + (lane >> 2);
#pragma unroll
        for (int nf = 0; nf < 8; nf++) {
            int c = col0 + wn * 64 + nf * 8 + 2 * (lane & 3);
            float2 v0 = make_float2(acc[mf][nf][0], acc[mf][nf][1]);
            float2 v1 = make_float2(acc[mf][nf][2], acc[mf][nf][3]);
            if (mode == 1) {
                *(float2*)&C[(size_t)m_base * DIM + c]       = v0;
                *(float2*)&C[(size_t)(m_base + 8) * DIM + c] = v1;
            } else {
                int which = c >> 9;
                int inner = c & 511;
                int h     = inner >> 6;
                int d     = inner & 63;
                __nv_bfloat16 *bh_, *bl_;
                if (which == 0) {
                    v0.x *= sc; v0.y *= sc; v1.x *= sc; v1.y *= sc;
                    bh_ = g_qhi; bl_ = g_qlo;
                } else if (which == 1) { bh_ = g_khi; bl_ = g_klo; }
                else                   { bh_ = g_vhi; bl_ = g_vlo; }
                int b0 = m_base >> 10, n0 = m_base & 1023;
                size_t off0 = ((size_t)((b0 * NHEADS + h) * SEQ + n0)) * DHEAD + d;
                *(uint32_t*)&bh_[off0] = pack_hi(v0.x, v0.y);
                *(uint32_t*)&bl_[off0] = pack_lo(v0.x, v0.y);
                int m1 = m_base + 8;
                int b1 = m1 >> 10, n1 = m1 & 1023;
                size_t off1 = ((size_t)((b1 * NHEADS + h) * SEQ + n1)) * DHEAD + d;
                *(uint32_t*)&bh_[off1] = pack_hi(v1.x, v1.y);
                *(uint32_t*)&bl_[off1] = pack_lo(v1.x, v1.y);
            }
        }
    }
}

// ============================================================================
// Flash attention on HMMA, 2-stage cp.async pipeline, exp2 softmax.
// CTA = 128 thr (4 warps), 64 q-rows; K-tiles of 64. Split-bf16 3-MMA.
// ============================================================================
#define KST   72
#define ABUF  9216                 /* 64*KST*2 bytes */
#define ASTAGE (4*ABUF)            /* Kh,Kl,Vh,Vl */

__global__ __launch_bounds__(128, 3) void attn_hmma_kernel()
{
    extern __shared__ char smem[];
    const uint32_t uS = smem_u32(smem);

    const int tx   = threadIdx.x;
    const int lane = tx & 31;
    const int wq   = tx >> 5;
    const int bh   = blockIdx.y;
    const int q0   = blockIdx.x * 64;
    const size_t base = (size_t)bh * SEQ * DHEAD;

    // ---- stage Q (64 rows) into stage-0 Kh/Kl, extract a-frags ----
#pragma unroll
    for (int t = 0; t < 4; t++) {
        int id = tx + t * 128;
        int r = id >> 3, c8 = (id & 7) << 3;
        uint32_t so = (uint32_t)(r * KST + c8) * 2;
        *(uint4*)(smem + so)        = *(const uint4*)&g_qhi[base + (size_t)(q0 + r) * DHEAD + c8];
        *(uint4*)(smem + ABUF + so) = *(const uint4*)&g_qlo[base + (size_t)(q0 + r) * DHEAD + c8];
    }
    __syncthreads();

    const int a_row  = lane & 15;
    const int a_half = lane >> 4;
    uint32_t qh[4][4], ql[4][4];
#pragma unroll
    for (int ks = 0; ks < 4; ks++) {
        uint32_t boff = (uint32_t)((wq * 16 + a_row) * KST + ks * 16) * 2 + a_half * 16;
        ldm_x4(qh[ks], uS + boff);
        ldm_x4(ql[ks], uS + ABUF + boff);
    }
    __syncthreads();

    const int cr = tx >> 1;
    const int cc = (tx & 1) << 5;
    auto issue = [&](int kt, int s) {
        uint32_t sb = uS + s * ASTAGE;
#pragma unroll
        for (int t = 0; t < 4; t++) {
            int c8 = cc + t * 8;
            uint32_t so = (uint32_t)(cr * KST + c8) * 2;
            size_t g = base + (size_t)(kt * 64 + cr) * DHEAD + c8;
            cp16(sb + so,            g_khi + g);
            cp16(sb + ABUF   + so,   g_klo + g);
            cp16(sb + 2*ABUF + so,   g_vhi + g);
            cp16(sb + 3*ABUF + so,   g_vlo + g);
        }
        cp_commit();
    };

    float oacc[8][4];
#pragma unroll
    for (int i = 0; i < 8; i++)
#pragma unroll
        for (int j = 0; j < 4; j++) oacc[i][j] = 0.f;
    float m0 = -INFINITY, m1 = -INFINITY, l0 = 0.f, l1 = 0.f;

    const int b_row  = (lane & 7) + ((lane >> 4) << 3);
    const int b_half = (lane >> 3) & 1;
    const int v_mat  = lane >> 3;
    const int v_row  = lane & 7;
    const int ra     = lane >> 2;
    const int c_in   = 2 * (lane & 3);

    issue(0, 0);
    for (int kt = 0; kt < 16; kt++) {
        if (kt + 1 < 16) { issue(kt + 1, (kt + 1) & 1); cp_wait<1>(); }
        else             { cp_wait<0>(); }
        __syncthreads();

        const uint32_t sb = uS + (kt & 1) * ASTAGE;
        const uint32_t uKh = sb, uKl = sb + ABUF, uVh = sb + 2*ABUF, uVl = sb + 3*ABUF;

        // ---- S = Q K^T (scores already in log2 domain via q prescale) ----
        float sacc[8][4];
#pragma unroll
        for (int i = 0; i < 8; i++)
#pragma unroll
            for (int j = 0; j < 4; j++) sacc[i][j] = 0.f;
#pragma unroll
        for (int nf2 = 0; nf2 < 4; nf2++) {
#pragma unroll
            for (int ks = 0; ks < 4; ks++) {
                uint32_t kh[4], kl[4];
                uint32_t boff = (uint32_t)((nf2 * 16 + b_row) * KST + ks * 16) * 2 + b_half * 16;
                ldm_x4(kh, uKh + boff);
                ldm_x4(kl, uKl + boff);
                // interleave the two acc chains between same-acc touches
                mma_bf16(sacc[2*nf2],   qh[ks], kh);
                mma_bf16(sacc[2*nf2+1], qh[ks], kh + 2);
                mma_bf16(sacc[2*nf2],   qh[ks], kl);
                mma_bf16(sacc[2*nf2+1], qh[ks], kl + 2);
                mma_bf16(sacc[2*nf2],   ql[ks], kh);
                mma_bf16(sacc[2*nf2+1], ql[ks], kh + 2);
            }
        }

        // ---- diagonal mask ----
        if (kt == blockIdx.x) {
            int row_a = q0 + wq * 16 + ra;
            int row_b = row_a + 8;
#pragma unroll
            for (int nf = 0; nf < 8; nf++) {
                int col = kt * 64 + nf * 8 + c_in;
                if (col     == row_a) sacc[nf][0] = -INFINITY;
                if (col + 1 == row_a) sacc[nf][1] = -INFINITY;
                if (col     == row_b) sacc[nf][2] = -INFINITY;
                if (col + 1 == row_b) sacc[nf][3] = -INFINITY;
            }
        }

        // ---- online softmax (base-2) ----
        float mt0 = -INFINITY, mt1 = -INFINITY;
#pragma unroll
        for (int nf = 0; nf < 8; nf++) {
            mt0 = fmaxf(mt0, fmaxf(sacc[nf][0], sacc[nf][1]));
            mt1 = fmaxf(mt1, fmaxf(sacc[nf][2], sacc[nf][3]));
        }
        mt0 = fmaxf(mt0, __shfl_xor_sync(0xffffffffu, mt0, 1));
        mt0 = fmaxf(mt0, __shfl_xor_sync(0xffffffffu, mt0, 2));
        mt1 = fmaxf(mt1, __shfl_xor_sync(0xffffffffu, mt1, 1));
        mt1 = fmaxf(mt1, __shfl_xor_sync(0xffffffffu, mt1, 2));

        float mn0 = fmaxf(m0, mt0), mn1 = fmaxf(m1, mt1);
        bool up0 = mn0 > m0, up1 = mn1 > m1;
        float ls0 = 0.f, ls1 = 0.f;
#pragma unroll
        for (int nf = 0; nf < 8; nf++) {
            float p0 = exp2f(sacc[nf][0] - mn0);
            float p1 = exp2f(sacc[nf][1] - mn0);
            float p2 = exp2f(sacc[nf][2] - mn1);
            float p3 = exp2f(sacc[nf][3] - mn1);
            ls0 += p0 + p1; ls1 += p2 + p3;
            sacc[nf][0] = p0; sacc[nf][1] = p1; sacc[nf][2] = p2; sacc[nf][3] = p3;
        }
        if (up0) {
            float cr0 = exp2f(m0 - mn0);      // exp2(-inf)=0 on first tile
            l0 *= cr0;
#pragma unroll
            for (int nf = 0; nf < 8; nf++) { oacc[nf][0] *= cr0; oacc[nf][1] *= cr0; }
            m0 = mn0;
        }
        if (up1) {
            float cr1 = exp2f(m1 - mn1);
            l1 *= cr1;
#pragma unroll
            for (int nf = 0; nf < 8; nf++) { oacc[nf][2] *= cr1; oacc[nf][3] *= cr1; }
            m1 = mn1;
        }
        l0 += ls0;  l1 += ls1;

        // ---- O += P V ----
#pragma unroll
        for (int kb = 0; kb < 4; kb++) {
            uint32_t pa_h[4], pa_l[4];
            pa_h[0] = pack_hi(sacc[2*kb][0],   sacc[2*kb][1]);
            pa_h[1] = pack_hi(sacc[2*kb][2],   sacc[2*kb][3]);
            pa_h[2] = pack_hi(sacc[2*kb+1][0], sacc[2*kb+1][1]);
            pa_h[3] = pack_hi(sacc[2*kb+1][2], sacc[2*kb+1][3]);
            pa_l[0] = pack_lo(sacc[2*kb][0],   sacc[2*kb][1]);
            pa_l[1] = pack_lo(sacc[2*kb][2],   sacc[2*kb][3]);
            pa_l[2] = pack_lo(sacc[2*kb+1][0], sacc[2*kb+1][1]);
            pa_l[3] = pack_lo(sacc[2*kb+1][2], sacc[2*kb+1][3]);
#pragma unroll
            for (int nf2 = 0; nf2 < 4; nf2++) {
                uint32_t boff = (uint32_t)((kb * 16 + (v_mat & 1) * 8 + v_row) * KST
                                           + nf2 * 16 + (v_mat >> 1) * 8) * 2;
                uint32_t vh[4], vl[4];
                ldm_x4t(vh, uVh + boff);
                ldm_x4t(vl, uVl + boff);
                mma_bf16(oacc[2*nf2],   pa_h, vh);
                mma_bf16(oacc[2*nf2+1], pa_h, vh + 2);
                mma_bf16(oacc[2*nf2],   pa_h, vl);
                mma_bf16(oacc[2*nf2+1], pa_h, vl + 2);
                mma_bf16(oacc[2*nf2],   pa_l, vh);
                mma_bf16(oacc[2*nf2+1], pa_l, vh + 2);
            }
        }
        __syncthreads();
    }

    // ---- finalize ----
    l0 += __shfl_xor_sync(0xffffffffu, l0, 1);
    l0 += __shfl_xor_sync(0xffffffffu, l0, 2);
    l1 += __shfl_xor_sync(0xffffffffu, l1, 1);
    l1 += __shfl_xor_sync(0xffffffffu, l1, 2);
    float inv0 = 1.f / l0, inv1 = 1.f / l1;

    const int b_ = bh >> 3, h = bh & 7;
    int row_a = q0 + wq * 16 + ra;
#pragma unroll
    for (int nf = 0; nf < 8; nf++) {
        int col = h * DHEAD + nf * 8 + c_in;
        size_t o0 = (size_t)(b_ * SEQ + row_a) * INNER + col;
        size_t o1 = (size_t)(b_ * SEQ + row_a + 8) * INNER + col;
        float a0 = oacc[nf][0] * inv0, a1 = oacc[nf][1] * inv0;
        float a2 = oacc[nf][2] * inv1, a3 = oacc[nf][3] * inv1;
        *(uint32_t*)&g_aohi[o0] = pack_hi(a0, a1);
        *(uint32_t*)&g_aolo[o0] = pack_lo(a0, a1);
        *(uint32_t*)&g_aohi[o1] = pack_hi(a2, a3);
        *(uint32_t*)&g_aolo[o1] = pack_lo(a2, a3);
    }
}

// ============================================================================
extern "C" void kernel_launch(void* const* d_in, const int* in_sizes, int n_in,
                              void* d_out, int out_size)
{
    const float* x    = nullptr;
    const float* wqkv = nullptr;
    const float* wout = nullptr;
    const float* temp = nullptr;
    for (int i = 0; i < n_in; i++) {
        switch (in_sizes[i]) {
            case 4194304: x    = (const float*)d_in[i]; break;
            case 786432:  wqkv = (const float*)d_in[i]; break;
            case 262144:  wout = (const float*)d_in[i]; break;
            case 1:       temp = (const float*)d_in[i]; break;
            default: break;
        }
    }
    float* out = (float*)d_out;

    static int attr_done = 0;
    if (!attr_done) {
        cudaFuncSetAttribute(gemm_hmma_kernel,
                             cudaFuncAttributeMaxDynamicSharedMemorySize, 2 * GSTAGE);
        cudaFuncSetAttribute(attn_hmma_kernel,
                             cudaFuncAttributeMaxDynamicSharedMemorySize, 2 * ASTAGE);
        attr_done = 1;
    }

    __nv_bfloat16 *wq_hi, *wq_lo, *wo_hi, *wo_lo, *xhi, *xlo, *aohi, *aolo;
    cudaGetSymbolAddress((void**)&wq_hi, g_wqkv_hi);
    cudaGetSymbolAddress((void**)&wq_lo, g_wqkv_lo);
    cudaGetSymbolAddress((void**)&wo_hi, g_wout_hi);
    cudaGetSymbolAddress((void**)&wo_lo, g_wout_lo);
    cudaGetSymbolAddress((void**)&xhi,  g_xhi);
    cudaGetSymbolAddress((void**)&xlo,  g_xlo);
    cudaGetSymbolAddress((void**)&aohi, g_aohi);
    cudaGetSymbolAddress((void**)&aolo, g_aolo);

    xsplit_kernel<<<M_TOT * DIM / (256 * 4), 256>>>(x);
    wsplit_kernel<<<dim3(48, 16), dim3(32, 32)>>>(wqkv, wq_hi, wq_lo, 3 * INNER);
    wsplit_kernel<<<dim3(16, 16), dim3(32, 32)>>>(wout, wo_hi, wo_lo, INNER);

    gemm_hmma_kernel<<<dim3(12, 64), 256, 2 * GSTAGE>>>(xhi, xlo, wq_hi, wq_lo,
                                                        nullptr, temp, 0);
    attn_hmma_kernel<<<dim3(16, 64), 128, 2 * ASTAGE>>>();
    gemm_hmma_kernel<<<dim3(4, 64), 256, 2 * GSTAGE>>>(aohi, aolo, wo_hi, wo_lo,
                                                       out, temp, 1);
    (void)out_size;
}

// round 9
// speedup vs baseline: 1.0224x; 1.0224x over previous
#include <cuda_runtime.h>
#include <cuda_bf16.h>
#include <math.h>
#include <stdint.h>

#define NB      8
#define SEQ     1024
#define DIM     512
#define NHEADS  8
#define DHEAD   64
#define INNER   512
#define M_TOT   (NB*SEQ)        /* 8192 */
#define BH      (NB*NHEADS)     /* 64 */

// ---- scratch (allocation-free: __device__ globals) ----
__device__ __nv_bfloat16 g_xhi [(size_t)M_TOT*DIM];     // pre-split x
__device__ __nv_bfloat16 g_xlo [(size_t)M_TOT*DIM];
__device__ __nv_bfloat16 g_aohi[(size_t)M_TOT*INNER];   // attn out, split
__device__ __nv_bfloat16 g_aolo[(size_t)M_TOT*INNER];
// pre-split bf16 q/k/v, [bh][n][d]; q has exp(temperature)*log2(e) folded in
__device__ __nv_bfloat16 g_qhi[(size_t)BH*SEQ*DHEAD];
__device__ __nv_bfloat16 g_qlo[(size_t)BH*SEQ*DHEAD];
__device__ __nv_bfloat16 g_khi[(size_t)BH*SEQ*DHEAD];
__device__ __nv_bfloat16 g_klo[(size_t)BH*SEQ*DHEAD];
__device__ __nv_bfloat16 g_vhi[(size_t)BH*SEQ*DHEAD];
__device__ __nv_bfloat16 g_vlo[(size_t)BH*SEQ*DHEAD];
// pre-transposed + split weights: [n][k] bf16
__device__ __nv_bfloat16 g_wqkv_hi[(size_t)3*INNER*DIM];
__device__ __nv_bfloat16 g_wqkv_lo[(size_t)3*INNER*DIM];
__device__ __nv_bfloat16 g_wout_hi[(size_t)DIM*INNER];
__device__ __nv_bfloat16 g_wout_lo[(size_t)DIM*INNER];

// ========================== helpers ===========================
__device__ __forceinline__ uint32_t smem_u32(const void* p) {
    uint32_t a;
    asm("{ .reg .u64 t; cvta.to.shared.u64 t, %1; cvt.u32.u64 %0, t; }" : "=r"(a) : "l"(p));
    return a;
}
__device__ __forceinline__ void ldm_x4(uint32_t* f, uint32_t addr) {
    asm volatile("ldmatrix.sync.aligned.m8n8.x4.shared.b16 {%0,%1,%2,%3}, [%4];"
                 : "=r"(f[0]), "=r"(f[1]), "=r"(f[2]), "=r"(f[3]) : "r"(addr));
}
__device__ __forceinline__ void ldm_x4t(uint32_t* f, uint32_t addr) {
    asm volatile("ldmatrix.sync.aligned.m8n8.x4.trans.shared.b16 {%0,%1,%2,%3}, [%4];"
                 : "=r"(f[0]), "=r"(f[1]), "=r"(f[2]), "=r"(f[3]) : "r"(addr));
}
__device__ __forceinline__ void mma_bf16(float* d, const uint32_t* a, const uint32_t* b) {
    asm("mma.sync.aligned.m16n8k16.row.col.f32.bf16.bf16.f32 "
        "{%0,%1,%2,%3}, {%4,%5,%6,%7}, {%8,%9}, {%0,%1,%2,%3};"
        : "+f"(d[0]), "+f"(d[1]), "+f"(d[2]), "+f"(d[3])
        : "r"(a[0]), "r"(a[1]), "r"(a[2]), "r"(a[3]), "r"(b[0]), "r"(b[1]));
}
__device__ __forceinline__ uint32_t pack_hi(float x, float y) {
    __nv_bfloat162 h = {__float2bfloat16(x), __float2bfloat16(y)};
    return *(uint32_t*)&h;
}
__device__ __forceinline__ uint32_t pack_lo(float x, float y) {
    float rx = x - __bfloat162float(__float2bfloat16(x));
    float ry = y - __bfloat162float(__float2bfloat16(y));
    __nv_bfloat162 l = {__float2bfloat16(rx), __float2bfloat16(ry)};
    return *(uint32_t*)&l;
}
__device__ __forceinline__ void cp16(uint32_t sdst, const void* gsrc) {
    asm volatile("cp.async.cg.shared.global [%0], [%1], 16;" :: "r"(sdst), "l"(gsrc));
}
__device__ __forceinline__ void cp_commit() { asm volatile("cp.async.commit_group;"); }
template <int N> __device__ __forceinline__ void cp_wait() {
    asm volatile("cp.async.wait_group %0;" :: "n"(N));
}

// ============================================================================
// Prep kernels (unchanged)
// ============================================================================
__global__ __launch_bounds__(256) void xsplit_kernel(const float* __restrict__ X)
{
    size_t i = ((size_t)blockIdx.x * 256 + threadIdx.x) * 4;
    float4 v = *(const float4*)&X[i];
    *(uint2*)&g_xhi[i] = make_uint2(pack_hi(v.x, v.y), pack_hi(v.z, v.w));
    *(uint2*)&g_xlo[i] = make_uint2(pack_lo(v.x, v.y), pack_lo(v.z, v.w));
}

__global__ void wsplit_kernel(const float* __restrict__ W,
                              __nv_bfloat16* __restrict__ hi,
                              __nv_bfloat16* __restrict__ lo, int N)
{
    __shared__ float t[32][33];
    int n = blockIdx.x * 32 + threadIdx.x;
    int k = blockIdx.y * 32 + threadIdx.y;
    t[threadIdx.y][threadIdx.x] = W[(size_t)k * N + n];
    __syncthreads();
    int n2 = blockIdx.x * 32 + threadIdx.y;
    int k2 = blockIdx.y * 32 + threadIdx.x;
    float v = t[threadIdx.x][threadIdx.y];
    __nv_bfloat16 h = __float2bfloat16(v);
    hi[(size_t)n2 * DIM + k2] = h;
    lo[(size_t)n2 * DIM + k2] = __float2bfloat16(v - __bfloat162float(h));
}

// ============================================================================
// HMMA GEMM (unchanged from R8 structure)
// ============================================================================
#define BK   32
#define PAD  40
#define GST  10240
#define GSTAGE (4*GST)

__global__ __launch_bounds__(256, 2) void gemm_hmma_kernel(
    const __nv_bfloat16* __restrict__ Ahi,
    const __nv_bfloat16* __restrict__ Alo,
    const __nv_bfloat16* __restrict__ Bhi,
    const __nv_bfloat16* __restrict__ Blo,
    float* __restrict__ C, const float* __restrict__ temp, int mode)
{
    extern __shared__ char smem[];
    const uint32_t uS = smem_u32(smem);

    const int tx   = threadIdx.x;
    const int lane = tx & 31;
    const int wid  = tx >> 5;
    const int wm   = wid >> 1;
    const int wn   = wid & 1;
    const int row0 = blockIdx.y * 128;
    const int col0 = blockIdx.x * 128;

    const int cr = tx >> 2;
    const int cc = (tx & 3) << 3;
    auto issue = [&](int kc, int s) {
        uint32_t sb = uS + s * GSTAGE;
#pragma unroll
        for (int t = 0; t < 2; t++) {
            int r = cr + t * 64;
            uint32_t so = (uint32_t)(r * PAD + cc) * 2;
            size_t  ga = (size_t)(row0 + r) * DIM + kc + cc;
            size_t  gb = (size_t)(col0 + r) * DIM + kc + cc;
            cp16(sb + so,           Ahi + ga);
            cp16(sb + GST   + so,   Alo + ga);
            cp16(sb + 2*GST + so,   Bhi + gb);
            cp16(sb + 3*GST + so,   Blo + gb);
        }
        cp_commit();
    };

    float acc[2][8][4];
#pragma unroll
    for (int i = 0; i < 2; i++)
#pragma unroll
        for (int j = 0; j < 8; j++)
#pragma unroll
            for (int t = 0; t < 4; t++) acc[i][j][t] = 0.f;

    const int a_row  = lane & 15;
    const int a_half = lane >> 4;
    const int b_row  = (lane & 7) + ((lane >> 4) << 3);
    const int b_half = (lane >> 3) & 1;

    issue(0, 0);
    const int KITER = DIM / BK;
    for (int kc = 0; kc < KITER; kc++) {
        if (kc + 1 < KITER) { issue((kc + 1) * BK, (kc + 1) & 1); cp_wait<1>(); }
        else                { cp_wait<0>(); }
        __syncthreads();

        const uint32_t sb = uS + (kc & 1) * GSTAGE;
        const uint32_t uAhi = sb, uAlo = sb + GST, uBhi = sb + 2*GST, uBlo = sb + 3*GST;
#pragma unroll
        for (int kk = 0; kk < 2; kk++) {
            uint32_t afh[2][4], afl[2][4];
#pragma unroll
            for (int mf = 0; mf < 2; mf++) {
                uint32_t boff = (uint32_t)((wm * 32 + mf * 16 + a_row) * PAD + kk * 16) * 2
                              + a_half * 16;
                ldm_x4(afh[mf], uAhi + boff);
                ldm_x4(afl[mf], uAlo + boff);
            }
            uint32_t bfh[8][2], bfl[8][2];
#pragma unroll
            for (int nf2 = 0; nf2 < 4; nf2++) {
                uint32_t boff = (uint32_t)((wn * 64 + nf2 * 16 + b_row) * PAD + kk * 16) * 2
                              + b_half * 16;
                uint32_t th[4], tl[4];
                ldm_x4(th, uBhi + boff);
                ldm_x4(tl, uBlo + boff);
                bfh[nf2*2][0] = th[0]; bfh[nf2*2][1] = th[1];
                bfh[nf2*2+1][0] = th[2]; bfh[nf2*2+1][1] = th[3];
                bfl[nf2*2][0] = tl[0]; bfl[nf2*2][1] = tl[1];
                bfl[nf2*2+1][0] = tl[2]; bfl[nf2*2+1][1] = tl[3];
            }
#pragma unroll
            for (int mf = 0; mf < 2; mf++)
#pragma unroll
                for (int nf = 0; nf < 8; nf++)
                    mma_bf16(acc[mf][nf], afh[mf], bfh[nf]);
#pragma unroll
            for (int mf = 0; mf < 2; mf++)
#pragma unroll
                for (int nf = 0; nf < 8; nf++)
                    mma_bf16(acc[mf][nf], afh[mf], bfl[nf]);
#pragma unroll
            for (int mf = 0; mf < 2; mf++)
#pragma unroll
                for (int nf = 0; nf < 8; nf++)
                    mma_bf16(acc[mf][nf], afl[mf], bfh[nf]);
        }
        __syncthreads();
    }

    const float sc = (mode == 0) ? __expf(*temp) * 1.44269504f : 1.f;
#pragma unroll
    for (int mf = 0; mf < 2; mf++) {
        int m_base = row0 + wm * 32 + mf * 16 + (lane >> 2);
#pragma unroll
        for (int nf = 0; nf < 8; nf++) {
            int c = col0 + wn * 64 + nf * 8 + 2 * (lane & 3);
            float2 v0 = make_float2(acc[mf][nf][0], acc[mf][nf][1]);
            float2 v1 = make_float2(acc[mf][nf][2], acc[mf][nf][3]);
            if (mode == 1) {
                *(float2*)&C[(size_t)m_base * DIM + c]       = v0;
                *(float2*)&C[(size_t)(m_base + 8) * DIM + c] = v1;
            } else {
                int which = c >> 9;
                int inner = c & 511;
                int h     = inner >> 6;
                int d     = inner & 63;
                __nv_bfloat16 *bh_, *bl_;
                if (which == 0) {
                    v0.x *= sc; v0.y *= sc; v1.x *= sc; v1.y *= sc;
                    bh_ = g_qhi; bl_ = g_qlo;
                } else if (which == 1) { bh_ = g_khi; bl_ = g_klo; }
                else                   { bh_ = g_vhi; bl_ = g_vlo; }
                int b0 = m_base >> 10, n0 = m_base & 1023;
                size_t off0 = ((size_t)((b0 * NHEADS + h) * SEQ + n0)) * DHEAD + d;
                *(uint32_t*)&bh_[off0] = pack_hi(v0.x, v0.y);
                *(uint32_t*)&bl_[off0] = pack_lo(v0.x, v0.y);
                int m1 = m_base + 8;
                int b1 = m1 >> 10, n1 = m1 & 1023;
                size_t off1 = ((size_t)((b1 * NHEADS + h) * SEQ + n1)) * DHEAD + d;
                *(uint32_t*)&bh_[off1] = pack_hi(v1.x, v1.y);
                *(uint32_t*)&bl_[off1] = pack_lo(v1.x, v1.y);
            }
        }
    }
}

// ============================================================================
// Flash attention v2: q-block 128 rows, 4 warps, 32 q-rows (2 m-frags) per
// warp. K/V ldmatrix traffic amortized over 2x MMAs (0.042 B/MAC < port
// budget). 2-stage cp.async pipeline, exp2 softmax, split-bf16 3-MMA.
// ============================================================================
#define KST   72
#define ABUF  9216                 /* 64*KST*2 bytes */
#define ASTAGE (4*ABUF)            /* Kh,Kl,Vh,Vl */

__global__ __launch_bounds__(128, 2) void attn_hmma_kernel()
{
    extern __shared__ char smem[];
    const uint32_t uS = smem_u32(smem);

    const int tx   = threadIdx.x;
    const int lane = tx & 31;
    const int wq   = tx >> 5;
    const int bh   = blockIdx.y;
    const int q0   = blockIdx.x * 128;
    const size_t base = (size_t)bh * SEQ * DHEAD;

    // ---- stage Q (128 rows, hi+lo) into the 4 stage-0 buffers ----
    // buf0: qhi rows 0-63, buf1: qhi rows 64-127, buf2: qlo 0-63, buf3: qlo 64-127
#pragma unroll
    for (int t = 0; t < 8; t++) {
        int id = tx + t * 128;                 // 0..1023
        int r  = id >> 3, c8 = (id & 7) << 3;  // r 0..127
        uint32_t hb = (r < 64) ? 0u : (uint32_t)ABUF;
        uint32_t so = (uint32_t)((r & 63) * KST + c8) * 2;
        *(uint4*)(smem + hb + so)            = *(const uint4*)&g_qhi[base + (size_t)(q0 + r) * DHEAD + c8];
        *(uint4*)(smem + 2*ABUF + hb + so)   = *(const uint4*)&g_qlo[base + (size_t)(q0 + r) * DHEAD + c8];
    }
    __syncthreads();

    const int a_row  = lane & 15;
    const int a_half = lane >> 4;
    uint32_t qh[2][4][4], ql[2][4][4];
#pragma unroll
    for (int mf = 0; mf < 2; mf++) {
        int gr = wq * 32 + mf * 16 + a_row;    // 0..127, same 64-block per warp/mf
        uint32_t hb = (gr < 64) ? 0u : (uint32_t)ABUF;
#pragma unroll
        for (int ks = 0; ks < 4; ks++) {
            uint32_t boff = (uint32_t)((gr & 63) * KST + ks * 16) * 2 + a_half * 16;
            ldm_x4(qh[mf][ks], uS + hb + boff);
            ldm_x4(ql[mf][ks], uS + 2*ABUF + hb + boff);
        }
    }
    __syncthreads();

    const int cr = tx >> 1;
    const int cc = (tx & 1) << 5;
    auto issue = [&](int kt, int s) {
        uint32_t sb = uS + s * ASTAGE;
#pragma unroll
        for (int t = 0; t < 4; t++) {
            int c8 = cc + t * 8;
            uint32_t so = (uint32_t)(cr * KST + c8) * 2;
            size_t g = base + (size_t)(kt * 64 + cr) * DHEAD + c8;
            cp16(sb + so,            g_khi + g);
            cp16(sb + ABUF   + so,   g_klo + g);
            cp16(sb + 2*ABUF + so,   g_vhi + g);
            cp16(sb + 3*ABUF + so,   g_vlo + g);
        }
        cp_commit();
    };

    float oacc[2][8][4];
#pragma unroll
    for (int mf = 0; mf < 2; mf++)
#pragma unroll
        for (int i = 0; i < 8; i++)
#pragma unroll
            for (int j = 0; j < 4; j++) oacc[mf][i][j] = 0.f;
    float mrow[4] = {-INFINITY, -INFINITY, -INFINITY, -INFINITY};
    float lrow[4] = {0.f, 0.f, 0.f, 0.f};

    const int b_row  = (lane & 7) + ((lane >> 4) << 3);
    const int b_half = (lane >> 3) & 1;
    const int v_mat  = lane >> 3;
    const int v_row  = lane & 7;
    const int ra     = lane >> 2;
    const int c_in   = 2 * (lane & 3);

    issue(0, 0);
    for (int kt = 0; kt < 16; kt++) {
        if (kt + 1 < 16) { issue(kt + 1, (kt + 1) & 1); cp_wait<1>(); }
        else             { cp_wait<0>(); }
        __syncthreads();

        const uint32_t sb = uS + (kt & 1) * ASTAGE;
        const uint32_t uKh = sb, uKl = sb + ABUF, uVh = sb + 2*ABUF, uVl = sb + 3*ABUF;

        // ---- S = Q K^T: K frags loaded once, used by both m-frags ----
        float sacc[2][8][4];
#pragma unroll
        for (int mf = 0; mf < 2; mf++)
#pragma unroll
            for (int i = 0; i < 8; i++)
#pragma unroll
                for (int j = 0; j < 4; j++) sacc[mf][i][j] = 0.f;
#pragma unroll
        for (int nf2 = 0; nf2 < 4; nf2++) {
#pragma unroll
            for (int ks = 0; ks < 4; ks++) {
                uint32_t kh[4], kl[4];
                uint32_t boff = (uint32_t)((nf2 * 16 + b_row) * KST + ks * 16) * 2 + b_half * 16;
                ldm_x4(kh, uKh + boff);
                ldm_x4(kl, uKl + boff);
#pragma unroll
                for (int mf = 0; mf < 2; mf++) {
                    mma_bf16(sacc[mf][2*nf2],   qh[mf][ks], kh);
                    mma_bf16(sacc[mf][2*nf2+1], qh[mf][ks], kh + 2);
                    mma_bf16(sacc[mf][2*nf2],   qh[mf][ks], kl);
                    mma_bf16(sacc[mf][2*nf2+1], qh[mf][ks], kl + 2);
                    mma_bf16(sacc[mf][2*nf2],   ql[mf][ks], kh);
                    mma_bf16(sacc[mf][2*nf2+1], ql[mf][ks], kh + 2);
                }
            }
        }

        // ---- diagonal mask (q-block covers 64-key tiles 2bx and 2bx+1) ----
        if ((kt >> 1) == blockIdx.x) {
#pragma unroll
            for (int mf = 0; mf < 2; mf++) {
                int row_a = q0 + wq * 32 + mf * 16 + ra;
                int row_b = row_a + 8;
#pragma unroll
                for (int nf = 0; nf < 8; nf++) {
                    int col = kt * 64 + nf * 8 + c_in;
                    if (col     == row_a) sacc[mf][nf][0] = -INFINITY;
                    if (col + 1 == row_a) sacc[mf][nf][1] = -INFINITY;
                    if (col     == row_b) sacc[mf][nf][2] = -INFINITY;
                    if (col + 1 == row_b) sacc[mf][nf][3] = -INFINITY;
                }
            }
        }

        // ---- online softmax (base-2) ----
        float mt[4] = {-INFINITY, -INFINITY, -INFINITY, -INFINITY};
#pragma unroll
        for (int mf = 0; mf < 2; mf++)
#pragma unroll
            for (int nf = 0; nf < 8; nf++) {
                mt[2*mf]   = fmaxf(mt[2*mf],   fmaxf(sacc[mf][nf][0], sacc[mf][nf][1]));
                mt[2*mf+1] = fmaxf(mt[2*mf+1], fmaxf(sacc[mf][nf][2], sacc[mf][nf][3]));
            }
#pragma unroll
        for (int i = 0; i < 4; i++) {
            mt[i] = fmaxf(mt[i], __shfl_xor_sync(0xffffffffu, mt[i], 1));
            mt[i] = fmaxf(mt[i], __shfl_xor_sync(0xffffffffu, mt[i], 2));
        }

        float mn[4], ls[4] = {0.f, 0.f, 0.f, 0.f};
#pragma unroll
        for (int i = 0; i < 4; i++) mn[i] = fmaxf(mrow[i], mt[i]);
#pragma unroll
        for (int mf = 0; mf < 2; mf++)
#pragma unroll
            for (int nf = 0; nf < 8; nf++) {
                float p0 = exp2f(sacc[mf][nf][0] - mn[2*mf]);
                float p1 = exp2f(sacc[mf][nf][1] - mn[2*mf]);
                float p2 = exp2f(sacc[mf][nf][2] - mn[2*mf+1]);
                float p3 = exp2f(sacc[mf][nf][3] - mn[2*mf+1]);
                ls[2*mf] += p0 + p1; ls[2*mf+1] += p2 + p3;
                sacc[mf][nf][0] = p0; sacc[mf][nf][1] = p1;
                sacc[mf][nf][2] = p2; sacc[mf][nf][3] = p3;
            }
#pragma unroll
        for (int i = 0; i < 4; i++) {
            if (mn[i] > mrow[i]) {
                float cr_ = exp2f(mrow[i] - mn[i]);     // 0 on first tile
                lrow[i] *= cr_;
                int mf = i >> 1, j0 = (i & 1) * 2;
#pragma unroll
                for (int nf = 0; nf < 8; nf++) {
                    oacc[mf][nf][j0]     *= cr_;
                    oacc[mf][nf][j0 + 1] *= cr_;
                }
                mrow[i] = mn[i];
            }
            lrow[i] += ls[i];
        }

        // ---- O += P V: V frags loaded once, used by both m-frags ----
#pragma unroll
        for (int kb = 0; kb < 4; kb++) {
            uint32_t pa_h[2][4], pa_l[2][4];
#pragma unroll
            for (int mf = 0; mf < 2; mf++) {
                pa_h[mf][0] = pack_hi(sacc[mf][2*kb][0],   sacc[mf][2*kb][1]);
                pa_h[mf][1] = pack_hi(sacc[mf][2*kb][2],   sacc[mf][2*kb][3]);
                pa_h[mf][2] = pack_hi(sacc[mf][2*kb+1][0], sacc[mf][2*kb+1][1]);
                pa_h[mf][3] = pack_hi(sacc[mf][2*kb+1][2], sacc[mf][2*kb+1][3]);
                pa_l[mf][0] = pack_lo(sacc[mf][2*kb][0],   sacc[mf][2*kb][1]);
                pa_l[mf][1] = pack_lo(sacc[mf][2*kb][2],   sacc[mf][2*kb][3]);
                pa_l[mf][2] = pack_lo(sacc[mf][2*kb+1][0], sacc[mf][2*kb+1][1]);
                pa_l[mf][3] = pack_lo(sacc[mf][2*kb+1][2], sacc[mf][2*kb+1][3]);
            }
#pragma unroll
            for (int nf2 = 0; nf2 < 4; nf2++) {
                uint32_t boff = (uint32_t)((kb * 16 + (v_mat & 1) * 8 + v_row) * KST
                                           + nf2 * 16 + (v_mat >> 1) * 8) * 2;
                uint32_t vh[4], vl[4];
                ldm_x4t(vh, uVh + boff);
                ldm_x4t(vl, uVl + boff);
#pragma unroll
                for (int mf = 0; mf < 2; mf++) {
                    mma_bf16(oacc[mf][2*nf2],   pa_h[mf], vh);
                    mma_bf16(oacc[mf][2*nf2+1], pa_h[mf], vh + 2);
                    mma_bf16(oacc[mf][2*nf2],   pa_h[mf], vl);
                    mma_bf16(oacc[mf][2*nf2+1], pa_h[mf], vl + 2);
                    mma_bf16(oacc[mf][2*nf2],   pa_l[mf], vh);
                    mma_bf16(oacc[mf][2*nf2+1], pa_l[mf], vh + 2);
                }
            }
        }
        __syncthreads();
    }

    // ---- finalize ----
#pragma unroll
    for (int i = 0; i < 4; i++) {
        lrow[i] += __shfl_xor_sync(0xffffffffu, lrow[i], 1);
        lrow[i] += __shfl_xor_sync(0xffffffffu, lrow[i], 2);
    }

    const int b_ = bh >> 3, h = bh & 7;
#pragma unroll
    for (int mf = 0; mf < 2; mf++) {
        int row_a = q0 + wq * 32 + mf * 16 + ra;
        float inv0 = 1.f / lrow[2*mf], inv1 = 1.f / lrow[2*mf+1];
#pragma unroll
        for (int nf = 0; nf < 8; nf++) {
            int col = h * DHEAD + nf * 8 + c_in;
            size_t o0 = (size_t)(b_ * SEQ + row_a) * INNER + col;
            size_t o1 = (size_t)(b_ * SEQ + row_a + 8) * INNER + col;
            float a0 = oacc[mf][nf][0] * inv0, a1 = oacc[mf][nf][1] * inv0;
            float a2 = oacc[mf][nf][2] * inv1, a3 = oacc[mf][nf][3] * inv1;
            *(uint32_t*)&g_aohi[o0] = pack_hi(a0, a1);
            *(uint32_t*)&g_aolo[o0] = pack_lo(a0, a1);
            *(uint32_t*)&g_aohi[o1] = pack_hi(a2, a3);
            *(uint32_t*)&g_aolo[o1] = pack_lo(a2, a3);
        }
    }
}

// ============================================================================
extern "C" void kernel_launch(void* const* d_in, const int* in_sizes, int n_in,
                              void* d_out, int out_size)
{
    const float* x    = nullptr;
    const float* wqkv = nullptr;
    const float* wout = nullptr;
    const float* temp = nullptr;
    for (int i = 0; i < n_in; i++) {
        switch (in_sizes[i]) {
            case 4194304: x    = (const float*)d_in[i]; break;
            case 786432:  wqkv = (const float*)d_in[i]; break;
            case 262144:  wout = (const float*)d_in[i]; break;
            case 1:       temp = (const float*)d_in[i]; break;
            default: break;
        }
    }
    float* out = (float*)d_out;

    static int attr_done = 0;
    if (!attr_done) {
        cudaFuncSetAttribute(gemm_hmma_kernel,
                             cudaFuncAttributeMaxDynamicSharedMemorySize, 2 * GSTAGE);
        cudaFuncSetAttribute(attn_hmma_kernel,
                             cudaFuncAttributeMaxDynamicSharedMemorySize, 2 * ASTAGE);
        attr_done = 1;
    }

    __nv_bfloat16 *wq_hi, *wq_lo, *wo_hi, *wo_lo, *xhi, *xlo, *aohi, *aolo;
    cudaGetSymbolAddress((void**)&wq_hi, g_wqkv_hi);
    cudaGetSymbolAddress((void**)&wq_lo, g_wqkv_lo);
    cudaGetSymbolAddress((void**)&wo_hi, g_wout_hi);
    cudaGetSymbolAddress((void**)&wo_lo, g_wout_lo);
    cudaGetSymbolAddress((void**)&xhi,  g_xhi);
    cudaGetSymbolAddress((void**)&xlo,  g_xlo);
    cudaGetSymbolAddress((void**)&aohi, g_aohi);
    cudaGetSymbolAddress((void**)&aolo, g_aolo);

    xsplit_kernel<<<M_TOT * DIM / (256 * 4), 256>>>(x);
    wsplit_kernel<<<dim3(48, 16), dim3(32, 32)>>>(wqkv, wq_hi, wq_lo, 3 * INNER);
    wsplit_kernel<<<dim3(16, 16), dim3(32, 32)>>>(wout, wo_hi, wo_lo, INNER);

    gemm_hmma_kernel<<<dim3(12, 64), 256, 2 * GSTAGE>>>(xhi, xlo, wq_hi, wq_lo,
                                                        nullptr, temp, 0);
    attn_hmma_kernel<<<dim3(8, 64), 128, 2 * ASTAGE>>>();
    gemm_hmma_kernel<<<dim3(4, 64), 256, 2 * GSTAGE>>>(aohi, aolo, wo_hi, wo_lo,
                                                       out, temp, 1);
    (void)out_size;
}